// round 13
// baseline (speedup 1.0000x reference)
#include <cuda_runtime.h>
#include <cuda_bf16.h>
#include <cstdint>

// Problem constants
#define NW 100000
#define NS 50000
#define NE 1000000
#define IN_DIM 256
#define D 64

// ---------------- scratch (static device arrays; no runtime alloc) ----------
__device__ float g_zw[NW * D];   // word-node projections  z_w
__device__ float g_Aw[NW * D];   // z_w @ Wg_a^T
__device__ float g_zs[NS * D];   // sentence-node projections z_s
__device__ float g_As[NS * D];   // z_s @ Wg_a^T
__device__ float g_Bs[NS * D];   // z_s @ Wg_b^T
__device__ float g_denom[NS];    // softmax denominators

// ---------------- init: zero denom + output ---------------------------------
__global__ void init_kernel(float* __restrict__ out) {
    int i = blockIdx.x * blockDim.x + threadIdx.x;
    if (i < NS * D) out[i] = 0.f;
    if (i < NS) g_denom[i] = 0.f;
}

// ---------------- tiled SGEMM:  C[M,64] = A[M,K] * B[64,K]^T ----------------
// BM=64, BN=64 (full N), BK=16, 256 threads, 4x4 register tile per thread.
// Inner loop uses packed fma.rn.f32x2 (FFMA2): A staged as duplicated pairs
// (a,a) in shared so the pair operand is one broadcast LDS.128; B pairs come
// free from float4 alignment. 3 LDS.128 + 8 FFMA2 per 512 warp-MACs.
__global__ __launch_bounds__(256)
void gemm_nt64(const float* __restrict__ A, int lda,
               const float* __restrict__ B, int ldb,
               float* __restrict__ C, int M, int K) {
    __shared__ __align__(16) float2 Asd[16][66];   // duplicated pairs (a,a)
    __shared__ __align__(16) float  Bs[16][68];
    const int tid = threadIdx.x;
    const int tx = tid & 15;        // 0..15 -> N (4 cols each)
    const int ty = tid >> 4;        // 0..15 -> M (4 rows each)
    const int row0 = blockIdx.x * 64;

    unsigned long long acc2[4][2];  // acc2[i][0]=(c0,c1) acc2[i][1]=(c2,c3)
#pragma unroll
    for (int i = 0; i < 4; i++) { acc2[i][0] = 0ull; acc2[i][1] = 0ull; }

    const int lm = tid >> 2;            // 0..63 row within tile
    const int lk = (tid & 3) << 2;      // 0,4,8,12 k offset

    for (int k0 = 0; k0 < K; k0 += 16) {
        float4 av = make_float4(0.f, 0.f, 0.f, 0.f);
        int gr = row0 + lm;
        if (gr < M) av = *(const float4*)(A + (size_t)gr * lda + k0 + lk);
        float4 bv = *(const float4*)(B + (size_t)lm * ldb + k0 + lk);
        Asd[lk + 0][lm] = make_float2(av.x, av.x);
        Asd[lk + 1][lm] = make_float2(av.y, av.y);
        Asd[lk + 2][lm] = make_float2(av.z, av.z);
        Asd[lk + 3][lm] = make_float2(av.w, av.w);
        Bs[lk + 0][lm] = bv.x; Bs[lk + 1][lm] = bv.y;
        Bs[lk + 2][lm] = bv.z; Bs[lk + 3][lm] = bv.w;
        __syncthreads();
#pragma unroll
        for (int kk = 0; kk < 16; kk++) {
            ulonglong2 ap01 = *(const ulonglong2*)(&Asd[kk][ty * 4]);
            ulonglong2 ap23 = *(const ulonglong2*)(&Asd[kk][ty * 4 + 2]);
            ulonglong2 bp   = *(const ulonglong2*)(&Bs[kk][tx * 4]);
            unsigned long long ap[4] = {ap01.x, ap01.y, ap23.x, ap23.y};
#pragma unroll
            for (int i = 0; i < 4; i++) {
                asm("fma.rn.f32x2 %0, %1, %2, %0;" : "+l"(acc2[i][0]) : "l"(ap[i]), "l"(bp.x));
                asm("fma.rn.f32x2 %0, %1, %2, %0;" : "+l"(acc2[i][1]) : "l"(ap[i]), "l"(bp.y));
            }
        }
        __syncthreads();
    }
#pragma unroll
    for (int i = 0; i < 4; i++) {
        int gr = row0 + ty * 4 + i;
        if (gr < M) {
            unsigned int c0, c1, c2, c3;
            asm("mov.b64 {%0,%1}, %2;" : "=r"(c0), "=r"(c1) : "l"(acc2[i][0]));
            asm("mov.b64 {%0,%1}, %2;" : "=r"(c2), "=r"(c3) : "l"(acc2[i][1]));
            *(float4*)(C + (size_t)gr * 64 + tx * 4) =
                make_float4(__uint_as_float(c0), __uint_as_float(c1),
                            __uint_as_float(c2), __uint_as_float(c3));
        }
    }
}

// ---------------- fused edge kernel -----------------------------------------
// One warp per edge; lane handles dims (2*lane, 2*lane+1).
// W_feat rows held in registers as packed f32x2; tfidf row broadcast via
// duplicated-pair shared staging -> 64 FFMA2 + 32 broadcast LDS.128 per edge.
// Software-pipelined (next edge prefetched); all once-streamed data (tfidf,
// src, dst) loaded with __ldcs (evict-first) so the 90 MB node tables stay
// L2-resident for the 4 gathers per edge-lane.
__global__ __launch_bounds__(128)
void edge_kernel(const float* __restrict__ tfidf,
                 const float* __restrict__ Wfeat,
                 const float* __restrict__ b_gate,
                 const float* __restrict__ w_attn,
                 const int*   __restrict__ src,
                 const int*   __restrict__ dst,
                 const int*   __restrict__ root,
                 float* __restrict__ out) {
    const int lane = threadIdx.x & 31;
    const int wrp  = threadIdx.x >> 5;
    const int gw   = blockIdx.x * 4 + wrp;
    const int nw   = gridDim.x * 4;
    const int d0   = lane << 1;

    // W_feat rows d0, d0+1 packed into 64 b64 regs: wp[k] = (W[d0][k], W[d0+1][k])
    unsigned long long wp[64];
#pragma unroll
    for (int kq = 0; kq < 16; kq++) {
        float4 a = *(const float4*)(Wfeat + d0 * 64 + kq * 4);
        float4 b = *(const float4*)(Wfeat + d0 * 64 + 64 + kq * 4);
        asm("mov.b64 %0, {%1, %2};" : "=l"(wp[kq * 4 + 0]) : "r"(__float_as_uint(a.x)), "r"(__float_as_uint(b.x)));
        asm("mov.b64 %0, {%1, %2};" : "=l"(wp[kq * 4 + 1]) : "r"(__float_as_uint(a.y)), "r"(__float_as_uint(b.y)));
        asm("mov.b64 %0, {%1, %2};" : "=l"(wp[kq * 4 + 2]) : "r"(__float_as_uint(a.z)), "r"(__float_as_uint(b.z)));
        asm("mov.b64 %0, {%1, %2};" : "=l"(wp[kq * 4 + 3]) : "r"(__float_as_uint(a.w)), "r"(__float_as_uint(b.w)));
    }
    const float2 b2  = *(const float2*)(b_gate + d0);
    const float2 wa2 = *(const float2*)(w_attn + d0);

    __shared__ __align__(16) float2 trp[4][64];   // duplicated pairs (t_k, t_k)

    // ---- prologue: fetch edge gw's data (streaming loads, evict-first) ----
    int   s_cur = 0, d_cur = 0, r_cur = 0;
    float2 t_cur = make_float2(0.f, 0.f);
    if (gw < NE) {
        s_cur = __ldcs(src + gw);
        d_cur = __ldcs(dst + gw);
        r_cur = root[d_cur];
        t_cur = __ldcs((const float2*)(tfidf + (size_t)gw * 64 + d0));
    }

    for (int e = gw; e < NE; e += nw) {
        const int s = s_cur, d = d_cur, r = r_cur;

        // stage current tfidf pair into shared for warp-wide broadcast
        trp[wrp][d0]     = make_float2(t_cur.x, t_cur.x);
        trp[wrp][d0 + 1] = make_float2(t_cur.y, t_cur.y);
        __syncwarp();

        // ---- prefetch NEXT edge (overlaps with matvec + gather + math) ----
        const int en = e + nw;
        if (en < NE) {
            s_cur = __ldcs(src + en);
            d_cur = __ldcs(dst + en);
            r_cur = root[d_cur];
            t_cur = __ldcs((const float2*)(tfidf + (size_t)en * 64 + d0));
        }

        // issue node gathers for current edge early (independent of matvec)
        const float2 zs2 = *(const float2*)(g_zw + (size_t)s * 64 + d0);
        const float2 zd2 = *(const float2*)(g_zs + (size_t)d * 64 + d0);
        const float2 a2  = r ? *(const float2*)(g_Aw + (size_t)s * 64 + d0)
                             : *(const float2*)(g_As + (size_t)d * 64 + d0);
        const float2 bs2 = *(const float2*)(g_Bs + (size_t)d * 64 + d0);

        // dfeat matvec: acc = sum_k wp[k] * (t_k, t_k)
        unsigned long long acc = 0ull;  // (0.f, 0.f)
#pragma unroll
        for (int k = 0; k < 64; k += 2) {
            ulonglong2 tq = *(const ulonglong2*)(&trp[wrp][k]);
            asm("fma.rn.f32x2 %0, %1, %2, %0;" : "+l"(acc) : "l"(wp[k]),     "l"(tq.x));
            asm("fma.rn.f32x2 %0, %1, %2, %0;" : "+l"(acc) : "l"(wp[k + 1]), "l"(tq.y));
        }
        __syncwarp();
        unsigned int dlo, dhi;
        asm("mov.b64 {%0, %1}, %2;" : "=r"(dlo), "=r"(dhi) : "l"(acc));
        const float dfx = __uint_as_float(dlo);
        const float dfy = __uint_as_float(dhi);

        const float gx = a2.x + bs2.x + b2.x;
        const float gy = a2.y + bs2.y + b2.y;
        const float gatex = __fdividef(1.f, 1.f + __expf(-gx));
        const float gatey = __fdividef(1.f, 1.f + __expf(-gy));
        const float z2x = r ? zs2.x : zd2.x;
        const float z2y = r ? zs2.y : zd2.y;
        const float ex2x = __expf(2.f * z2x);
        const float ex2y = __expf(2.f * z2y);
        const float thx = __fdividef(ex2x - 1.f, ex2x + 1.f);
        const float thy = __fdividef(ex2y - 1.f, ex2y + 1.f);
        const float z22x = gatex * thx + (1.f - gatex) * zd2.x;
        const float z22y = gatey * thy + (1.f - gatey) * zd2.y;
        float vx = z22x + zs2.x + dfx;
        float vy = z22y + zs2.y + dfy;
        vx = vx > 0.f ? vx : 0.01f * vx;
        vy = vy > 0.f ? vy : 0.01f * vy;

        float p = vx * wa2.x + vy * wa2.y;
#pragma unroll
        for (int o = 16; o; o >>= 1) p += __shfl_xor_sync(0xffffffffu, p, o);

        const float ew = __expf(p);                     // exp(e), no max-shift needed
        float2 contrib = make_float2(ew * zs2.x, ew * zs2.y);
        atomicAdd((float2*)out + ((size_t)d * 32 + lane), contrib);
        if (lane == 0) atomicAdd(&g_denom[d], ew);
    }
}

// ---------------- finalize: divide by denom ----------------------------------
__global__ void finalize_kernel(float* __restrict__ out) {
    int i = blockIdx.x * blockDim.x + threadIdx.x;
    if (i < NS * D) {
        float dn = g_denom[i >> 6];
        out[i] = (dn > 0.f) ? __fdividef(out[i], dn) : 0.f;
    }
}

// ---------------- launch ------------------------------------------------------
extern "C" void kernel_launch(void* const* d_in, const int* in_sizes, int n_in,
                              void* d_out, int out_size) {
    const float* h      = (const float*)d_in[0];   // [NW, 256]
    const float* o      = (const float*)d_in[1];   // [NS, 64]
    const float* tfidf  = (const float*)d_in[2];   // [E, 64]
    const float* W_fc   = (const float*)d_in[3];   // [64, 256]
    const float* W_fc1  = (const float*)d_in[4];   // [64, 64]
    const float* W_feat = (const float*)d_in[5];   // [64, 64]
    const float* w_attn = (const float*)d_in[6];   // [64]
    const float* W_gate = (const float*)d_in[7];   // [64, 128]
    const float* b_gate = (const float*)d_in[8];   // [64]
    const int*   src    = (const int*)d_in[9];     // [E]
    const int*   dst    = (const int*)d_in[10];    // [E]
    const int*   root   = (const int*)d_in[11];    // [NS]
    float* out = (float*)d_out;

    float *p_zw, *p_Aw, *p_zs, *p_As, *p_Bs;
    cudaGetSymbolAddress((void**)&p_zw, g_zw);
    cudaGetSymbolAddress((void**)&p_Aw, g_Aw);
    cudaGetSymbolAddress((void**)&p_zs, g_zs);
    cudaGetSymbolAddress((void**)&p_As, g_As);
    cudaGetSymbolAddress((void**)&p_Bs, g_Bs);

    // zero denom + output
    init_kernel<<<(NS * D + 255) / 256, 256>>>(out);

    // node projections
    gemm_nt64<<<(NW + 63) / 64, 256>>>(h, IN_DIM, W_fc, IN_DIM, p_zw, NW, IN_DIM); // z_w
    gemm_nt64<<<(NS + 63) / 64, 256>>>(o, 64, W_fc1, 64, p_zs, NS, 64);            // z_s
    gemm_nt64<<<(NW + 63) / 64, 256>>>(p_zw, 64, W_gate, 128, p_Aw, NW, 64);       // A_w
    gemm_nt64<<<(NS + 63) / 64, 256>>>(p_zs, 64, W_gate, 128, p_As, NS, 64);       // A_s
    gemm_nt64<<<(NS + 63) / 64, 256>>>(p_zs, 64, W_gate + 64, 128, p_Bs, NS, 64);  // B_s

    // fused edge pass (e, exp, scatter-accumulate)
    edge_kernel<<<608, 128>>>(tfidf, W_feat, b_gate, w_attn, src, dst, root, out);

    // divide by denominators
    finalize_kernel<<<(NS * D + 255) / 256, 256>>>(out);
}

// round 15
// speedup vs baseline: 1.9938x; 1.9938x over previous
#include <cuda_runtime.h>
#include <cuda_bf16.h>
#include <cstdint>

// Problem constants
#define NW 100000
#define NS 50000
#define NE 1000000
#define IN_DIM 256
#define D 64

// ---------------- scratch (static device arrays; no runtime alloc) ----------
__device__ float g_zw[NW * D];     // word-node projections  z_w
__device__ float g_Aw[NW * D];     // z_w @ Wg_a^T
__device__ float g_zs[NS * D];     // sentence-node projections z_s
__device__ float g_As[NS * D];     // z_s @ Wg_a^T
__device__ float g_Bs[NS * D];     // z_s @ Wg_b^T
__device__ float g_denom[NS];      // softmax denominators
__device__ float g_dfeat[(size_t)NE * D];  // tfidf @ W_feat^T (256 MB)

// ---------------- init: zero denom + output ---------------------------------
__global__ void init_kernel(float* __restrict__ out) {
    int i = blockIdx.x * blockDim.x + threadIdx.x;
    if (i < NS * D) out[i] = 0.f;
    if (i < NS) g_denom[i] = 0.f;
}

// ---------------- tiled SGEMM:  C[M,64] = A[M,K] * B[64,K]^T ----------------
// BM=64, BN=64 (full N), BK=16, 256 threads, 4x4 register tile per thread.
// Packed fma.rn.f32x2 inner loop (measured ~45 TMAC/s on this shape).
__global__ __launch_bounds__(256)
void gemm_nt64(const float* __restrict__ A, int lda,
               const float* __restrict__ B, int ldb,
               float* __restrict__ C, int M, int K) {
    __shared__ __align__(16) float2 Asd[16][66];   // duplicated pairs (a,a)
    __shared__ __align__(16) float  Bs[16][68];
    const int tid = threadIdx.x;
    const int tx = tid & 15;        // 0..15 -> N (4 cols each)
    const int ty = tid >> 4;        // 0..15 -> M (4 rows each)
    const int row0 = blockIdx.x * 64;

    unsigned long long acc2[4][2];
#pragma unroll
    for (int i = 0; i < 4; i++) { acc2[i][0] = 0ull; acc2[i][1] = 0ull; }

    const int lm = tid >> 2;            // 0..63 row within tile
    const int lk = (tid & 3) << 2;      // 0,4,8,12 k offset

    for (int k0 = 0; k0 < K; k0 += 16) {
        float4 av = make_float4(0.f, 0.f, 0.f, 0.f);
        int gr = row0 + lm;
        if (gr < M) av = *(const float4*)(A + (size_t)gr * lda + k0 + lk);
        float4 bv = *(const float4*)(B + (size_t)lm * ldb + k0 + lk);
        Asd[lk + 0][lm] = make_float2(av.x, av.x);
        Asd[lk + 1][lm] = make_float2(av.y, av.y);
        Asd[lk + 2][lm] = make_float2(av.z, av.z);
        Asd[lk + 3][lm] = make_float2(av.w, av.w);
        Bs[lk + 0][lm] = bv.x; Bs[lk + 1][lm] = bv.y;
        Bs[lk + 2][lm] = bv.z; Bs[lk + 3][lm] = bv.w;
        __syncthreads();
#pragma unroll
        for (int kk = 0; kk < 16; kk++) {
            ulonglong2 ap01 = *(const ulonglong2*)(&Asd[kk][ty * 4]);
            ulonglong2 ap23 = *(const ulonglong2*)(&Asd[kk][ty * 4 + 2]);
            ulonglong2 bp   = *(const ulonglong2*)(&Bs[kk][tx * 4]);
            unsigned long long ap[4] = {ap01.x, ap01.y, ap23.x, ap23.y};
#pragma unroll
            for (int i = 0; i < 4; i++) {
                asm("fma.rn.f32x2 %0, %1, %2, %0;" : "+l"(acc2[i][0]) : "l"(ap[i]), "l"(bp.x));
                asm("fma.rn.f32x2 %0, %1, %2, %0;" : "+l"(acc2[i][1]) : "l"(ap[i]), "l"(bp.y));
            }
        }
        __syncthreads();
    }
#pragma unroll
    for (int i = 0; i < 4; i++) {
        int gr = row0 + ty * 4 + i;
        if (gr < M) {
            unsigned int c0, c1, c2, c3;
            asm("mov.b64 {%0,%1}, %2;" : "=r"(c0), "=r"(c1) : "l"(acc2[i][0]));
            asm("mov.b64 {%0,%1}, %2;" : "=r"(c2), "=r"(c3) : "l"(acc2[i][1]));
            *(float4*)(C + (size_t)gr * 64 + tx * 4) =
                make_float4(__uint_as_float(c0), __uint_as_float(c1),
                            __uint_as_float(c2), __uint_as_float(c3));
        }
    }
}

// ---------------- lightweight fused edge kernel ------------------------------
// One warp per edge iteration; lane handles dims (2*lane, 2*lane+1).
// dfeat precomputed by GEMM -> no W_feat in registers, no shared staging,
// no long FMA chain. ~40 regs -> 48 warps/SM; latency hidden by occupancy.
__global__ __launch_bounds__(256)
void edge_kernel(const float* __restrict__ dfeat,
                 const float* __restrict__ b_gate,
                 const float* __restrict__ w_attn,
                 const int*   __restrict__ src,
                 const int*   __restrict__ dst,
                 const int*   __restrict__ root,
                 float* __restrict__ out) {
    const int lane = threadIdx.x & 31;
    const int wrp  = threadIdx.x >> 5;
    const int gw   = blockIdx.x * 8 + wrp;
    const int nw   = gridDim.x * 8;
    const int d0   = lane << 1;

    const float2 b2  = *(const float2*)(b_gate + d0);
    const float2 wa2 = *(const float2*)(w_attn + d0);

    for (int e = gw; e < NE; e += nw) {
        const int s = __ldcs(src + e);
        const int d = __ldcs(dst + e);
        const int r = root[d];

        // streamed per-edge dfeat (evict-first) + node gathers (L2-resident)
        const float2 df2 = __ldcs((const float2*)(dfeat + (size_t)e * 64 + d0));
        const float2 zs2 = *(const float2*)(g_zw + (size_t)s * 64 + d0);
        const float2 zd2 = *(const float2*)(g_zs + (size_t)d * 64 + d0);
        const float2 a2  = r ? *(const float2*)(g_Aw + (size_t)s * 64 + d0)
                             : *(const float2*)(g_As + (size_t)d * 64 + d0);
        const float2 bs2 = *(const float2*)(g_Bs + (size_t)d * 64 + d0);

        const float gx = a2.x + bs2.x + b2.x;
        const float gy = a2.y + bs2.y + b2.y;
        const float gatex = __fdividef(1.f, 1.f + __expf(-gx));
        const float gatey = __fdividef(1.f, 1.f + __expf(-gy));
        const float z2x = r ? zs2.x : zd2.x;
        const float z2y = r ? zs2.y : zd2.y;
        const float ex2x = __expf(2.f * z2x);
        const float ex2y = __expf(2.f * z2y);
        const float thx = __fdividef(ex2x - 1.f, ex2x + 1.f);
        const float thy = __fdividef(ex2y - 1.f, ex2y + 1.f);
        const float z22x = gatex * thx + (1.f - gatex) * zd2.x;
        const float z22y = gatey * thy + (1.f - gatey) * zd2.y;
        float vx = z22x + zs2.x + df2.x;
        float vy = z22y + zs2.y + df2.y;
        vx = vx > 0.f ? vx : 0.01f * vx;
        vy = vy > 0.f ? vy : 0.01f * vy;

        float p = vx * wa2.x + vy * wa2.y;
#pragma unroll
        for (int o = 16; o; o >>= 1) p += __shfl_xor_sync(0xffffffffu, p, o);

        const float ew = __expf(p);                     // exp(e), no max-shift needed
        float2 contrib = make_float2(ew * zs2.x, ew * zs2.y);
        atomicAdd((float2*)out + ((size_t)d * 32 + lane), contrib);
        if (lane == 0) atomicAdd(&g_denom[d], ew);
    }
}

// ---------------- finalize: divide by denom ----------------------------------
__global__ void finalize_kernel(float* __restrict__ out) {
    int i = blockIdx.x * blockDim.x + threadIdx.x;
    if (i < NS * D) {
        float dn = g_denom[i >> 6];
        out[i] = (dn > 0.f) ? __fdividef(out[i], dn) : 0.f;
    }
}

// ---------------- launch ------------------------------------------------------
extern "C" void kernel_launch(void* const* d_in, const int* in_sizes, int n_in,
                              void* d_out, int out_size) {
    const float* h      = (const float*)d_in[0];   // [NW, 256]
    const float* o      = (const float*)d_in[1];   // [NS, 64]
    const float* tfidf  = (const float*)d_in[2];   // [E, 64]
    const float* W_fc   = (const float*)d_in[3];   // [64, 256]
    const float* W_fc1  = (const float*)d_in[4];   // [64, 64]
    const float* W_feat = (const float*)d_in[5];   // [64, 64]
    const float* w_attn = (const float*)d_in[6];   // [64]
    const float* W_gate = (const float*)d_in[7];   // [64, 128]
    const float* b_gate = (const float*)d_in[8];   // [64]
    const int*   src    = (const int*)d_in[9];     // [E]
    const int*   dst    = (const int*)d_in[10];    // [E]
    const int*   root   = (const int*)d_in[11];    // [NS]
    float* out = (float*)d_out;

    float *p_zw, *p_Aw, *p_zs, *p_As, *p_Bs, *p_df;
    cudaGetSymbolAddress((void**)&p_zw, g_zw);
    cudaGetSymbolAddress((void**)&p_Aw, g_Aw);
    cudaGetSymbolAddress((void**)&p_zs, g_zs);
    cudaGetSymbolAddress((void**)&p_As, g_As);
    cudaGetSymbolAddress((void**)&p_Bs, g_Bs);
    cudaGetSymbolAddress((void**)&p_df, g_dfeat);

    // zero denom + output
    init_kernel<<<(NS * D + 255) / 256, 256>>>(out);

    // node projections
    gemm_nt64<<<(NW + 63) / 64, 256>>>(h, IN_DIM, W_fc, IN_DIM, p_zw, NW, IN_DIM); // z_w
    gemm_nt64<<<(NS + 63) / 64, 256>>>(o, 64, W_fc1, 64, p_zs, NS, 64);            // z_s
    gemm_nt64<<<(NW + 63) / 64, 256>>>(p_zw, 64, W_gate, 128, p_Aw, NW, 64);       // A_w
    gemm_nt64<<<(NS + 63) / 64, 256>>>(p_zs, 64, W_gate, 128, p_As, NS, 64);       // A_s
    gemm_nt64<<<(NS + 63) / 64, 256>>>(p_zs, 64, W_gate + 64, 128, p_Bs, NS, 64);  // B_s

    // per-edge feature projection as dense GEMM: dfeat = tfidf @ W_feat^T
    gemm_nt64<<<(NE + 63) / 64, 256>>>(tfidf, 64, W_feat, 64, p_df, NE, 64);

    // fused edge pass (e, exp, scatter-accumulate) — lightweight, high-occupancy
    edge_kernel<<<2048, 256>>>(p_df, b_gate, w_attn, src, dst, root, out);

    // divide by denominators
    finalize_kernel<<<(NS * D + 255) / 256, 256>>>(out);
}